// round 15
// baseline (speedup 1.0000x reference)
#include <cuda_runtime.h>
#include <cuda_fp16.h>
#include <mma.h>
#include <cstddef>
#include <cstdint>

using namespace nvcuda;

#define V    6912
#define G4   27648   // 4*V
#define BSZ  16
#define TT   8
#define TR   4
#define NBLK 432     // persistent grid size

// ---------------- device scratch (no allocation allowed) ----------------
// Gate-interleaved layouts: index n' = j*4 + g  (g: 0=i,1=f,2=g,3=o)
__device__ __half g_whh16[(size_t)G4 * V];   // fp16 W_hh_enc, rows interleaved
__device__ __half g_x16 [128 * V];           // x fp16
__device__ __half g_h16 [2][BSZ * V];        // encoder h fp16, ping-pong
__device__ __half g_hd16[BSZ * TR * V];      // decoder h_d (fp16, fc_dec A)
__device__ float  g_xg  [128 * G4];          // xg, cols interleaved
__device__ float  g_bep [G4];                // b_enc permuted
__device__ float  g_bdp [G4];                // b_dec permuted
__device__ float  g_widp[G4];                // W_ih_dec permuted
__device__ unsigned g_bar;                   // persistent-kernel barrier counter

__device__ __forceinline__ float sigf(float x) { return 1.0f / (1.0f + expf(-x)); }

__device__ __forceinline__ uint4 pack8(float4 a, float4 b)
{
    __half2 h0 = __floats2half2_rn(a.x, a.y);
    __half2 h1 = __floats2half2_rn(a.z, a.w);
    __half2 h2 = __floats2half2_rn(b.x, b.y);
    __half2 h3 = __floats2half2_rn(b.z, b.w);
    uint4 u;
    u.x = *reinterpret_cast<unsigned*>(&h0);
    u.y = *reinterpret_cast<unsigned*>(&h1);
    u.z = *reinterpret_cast<unsigned*>(&h2);
    u.w = *reinterpret_cast<unsigned*>(&h3);
    return u;
}

// =====================================================================
// Prologue: blocks [0,432): x -> fp16; [432,540): permute b/W vectors;
// resets grid barrier; seeds out[0..15] with fc_enc bias.
// =====================================================================
__global__ void prep_conv_kernel(const float* __restrict__ x,
                                 const float* __restrict__ be,
                                 const float* __restrict__ bd,
                                 const float* __restrict__ wid,
                                 const float* __restrict__ feb,
                                 float* __restrict__ out)
{
    if (blockIdx.x == 0 && threadIdx.x == 0) g_bar = 0u;
    int bx = blockIdx.x;
    if (bx < 432) {
        int idx = bx * 256 + threadIdx.x;           // 432*256 = 128*V/8
        const float4* s = (const float4*)x + (size_t)idx * 2;
        ((uint4*)g_x16)[idx] = pack8(s[0], s[1]);
    } else {
        int idx = (bx - 432) * 256 + threadIdx.x;   // 108*256 = G4
        int src = (idx & 3) * V + (idx >> 2);
        g_bep[idx]  = be[src];
        g_bdp[idx]  = bd[src];
        g_widp[idx] = wid[src];
        if (bx == 539 && threadIdx.x < BSZ) out[threadIdx.x] = feb[0];
    }
}

// =====================================================================
// xg GEMM: BM=64 (grid.y = m-half), BN=128, BK=32, full K, direct store.
// =====================================================================
__global__ __launch_bounds__(256) void gemm_xg_kernel(const float* __restrict__ Wih)
{
    constexpr int BK = 32, BNB = 128, LDS = BK + 8;
    __shared__ __align__(16) __half sA[2][64][LDS];
    __shared__ __align__(16) __half sB[2][BNB][LDS];

    const int tid = threadIdx.x;
    const int n0  = blockIdx.x * BNB;
    const int m0  = blockIdx.y * 64;

    const int w  = tid >> 5;
    const int wm = w >> 2, wn = w & 3;

    wmma::fragment<wmma::accumulator, 16, 16, 16, float> acc[2][2];
#pragma unroll
    for (int i = 0; i < 2; i++)
#pragma unroll
        for (int j = 0; j < 2; j++) wmma::fill_fragment(acc[i][j], 0.0f);

    uint4 rb[2], ra;
    auto load = [&](int k0) {
#pragma unroll
        for (int p = 0; p < 2; p++) {
            int c = tid + p * 256;
            int row = c >> 2, kc = (c & 3) * 8;
            int nn = n0 + row;
            const float* s = Wih + ((size_t)(nn & 3) * V + (nn >> 2)) * V + k0 + kc;
            rb[p] = pack8(*(const float4*)s, *(const float4*)(s + 4));
        }
        {
            int row = tid >> 2, kc = (tid & 3) * 8;
            ra = *(const uint4*)(g_x16 + (size_t)(m0 + row) * V + k0 + kc);
        }
    };
    auto store = [&](int buf) {
#pragma unroll
        for (int p = 0; p < 2; p++) {
            int c = tid + p * 256;
            int row = c >> 2, kc = (c & 3) * 8;
            *(uint4*)(&sB[buf][row][kc]) = rb[p];
        }
        *(uint4*)(&sA[buf][tid >> 2][(tid & 3) * 8]) = ra;
    };

    load(0);
    store(0);
    load(BK);
    __syncthreads();

    const int niter = V / BK;   // 216
    for (int i = 0; i < niter; i++) {
        int p = i & 1;
        if (i + 1 < niter) store(p ^ 1);
        if (i + 2 < niter) load((i + 2) * BK);
#pragma unroll
        for (int kk = 0; kk < BK; kk += 16) {
            wmma::fragment<wmma::matrix_a, 16, 16, 16, __half, wmma::row_major> af[2];
            wmma::fragment<wmma::matrix_b, 16, 16, 16, __half, wmma::col_major> bf[2];
#pragma unroll
            for (int i_ = 0; i_ < 2; i_++)
                wmma::load_matrix_sync(af[i_], &sA[p][wm * 32 + i_ * 16][kk], LDS);
#pragma unroll
            for (int j_ = 0; j_ < 2; j_++)
                wmma::load_matrix_sync(bf[j_], &sB[p][wn * 32 + j_ * 16][kk], LDS);
#pragma unroll
            for (int i_ = 0; i_ < 2; i_++)
#pragma unroll
                for (int j_ = 0; j_ < 2; j_++)
                    wmma::mma_sync(acc[i_][j_], af[i_], bf[j_], acc[i_][j_]);
        }
        __syncthreads();
    }

#pragma unroll
    for (int i_ = 0; i_ < 2; i_++)
#pragma unroll
        for (int j_ = 0; j_ < 2; j_++)
            wmma::store_matrix_sync(
                g_xg + (size_t)(m0 + wm * 32 + i_ * 16) * G4 + n0 + wn * 32 + j_ * 16,
                acc[i_][j_], G4, wmma::mem_row_major);
}

// =====================================================================
// Persistent kernel: step0 + steps 1..7 (+fc_enc fold) + decoder +
// fc_dec + output scatter.  Grid 432, guaranteed 3 blocks/SM.
// =====================================================================
struct SMu {
    union {
        struct { __half A[3][16][136]; __half B[3][64][136]; } h;   // fp16 rec
        struct { __half A[2][16][72];  __half B[2][64][72];  } f;   // fp32 rec
        struct { __half A[2][64][72];  __half B[2][16][72];  } d;   // fc_dec
        struct { float R[8][16][32]; float F[16][64]; } ep;          // epilogues
    };
};

__device__ __forceinline__ void grid_bar(unsigned k)
{
    __threadfence();
    __syncthreads();
    if (threadIdx.x == 0) {
        atomicAdd(&g_bar, 1u);
        volatile unsigned* p = &g_bar;
        while (*p < k * (unsigned)NBLK) { }
    }
    __syncthreads();
}

__device__ __forceinline__ void combine8(float (*sR)[16][32], float (*sF)[64])
{
    int tid = threadIdx.x;
    for (int c = tid; c < 16 * 64; c += 256) {
        int m = c >> 6, n = c & 63;
        int f = n >> 4, cc = n & 15;
        sF[m][n] = sR[f][m][cc] + sR[f + 4][m][cc];
    }
}

// fp16-weight mainloop (BK=128, 3-stage cp.async) -> sm.ep.F
__device__ __forceinline__ void compute_f16(SMu& sm, const __half* __restrict__ hin,
                                            int n0)
{
    constexpr int BK = 128, STAGES = 3, LDS = 136;
    const int tid = threadIdx.x;
    const int w = tid >> 5, nf = w & 3, kh = w >> 2;
    const int niter = V / BK;   // 54

    wmma::fragment<wmma::accumulator, 16, 16, 16, float> acc;
    wmma::fill_fragment(acc, 0.0f);

    auto stage = [&](int s, int k0) {
#pragma unroll
        for (int p = 0; p < 4; p++) {
            int c = tid + p * 256;
            int row = c >> 4, kc = (c & 15) * 8;
            uint32_t d = (uint32_t)__cvta_generic_to_shared(&sm.h.B[s][row][kc]);
            const void* g = g_whh16 + (size_t)(n0 + row) * V + k0 + kc;
            asm volatile("cp.async.cg.shared.global [%0], [%1], 16;\n" :: "r"(d), "l"(g));
        }
        {
            int row = tid >> 4, kc = (tid & 15) * 8;
            uint32_t d = (uint32_t)__cvta_generic_to_shared(&sm.h.A[s][row][kc]);
            const void* g = hin + (size_t)row * V + k0 + kc;
            asm volatile("cp.async.cg.shared.global [%0], [%1], 16;\n" :: "r"(d), "l"(g));
        }
        asm volatile("cp.async.commit_group;\n");
    };

    int issued = 0;
    for (; issued < STAGES - 1; issued++) stage(issued, issued * BK);

    for (int i = 0; i < niter; i++) {
        asm volatile("cp.async.wait_group %0;\n" :: "n"(STAGES - 2));
        __syncthreads();
        if (issued < niter) { stage(issued % STAGES, issued * BK); issued++; }
        else                { asm volatile("cp.async.commit_group;\n"); }
        int s = i % STAGES;
        int kb = kh * 64;
#pragma unroll
        for (int kk = kb; kk < kb + 64; kk += 16) {
            wmma::fragment<wmma::matrix_a, 16, 16, 16, __half, wmma::row_major> af;
            wmma::fragment<wmma::matrix_b, 16, 16, 16, __half, wmma::col_major> bf;
            wmma::load_matrix_sync(af, &sm.h.A[s][0][kk], LDS);
            wmma::load_matrix_sync(bf, &sm.h.B[s][nf * 16][kk], LDS);
            wmma::mma_sync(acc, af, bf, acc);
        }
    }
    asm volatile("cp.async.wait_group 0;\n");
    __syncthreads();
    wmma::store_matrix_sync(&sm.ep.R[w][0][0], acc, 32, wmma::mem_row_major);
    __syncthreads();
    combine8(sm.ep.R, sm.ep.F);
    __syncthreads();
}

// fp32-weight mainloop (BK=64, reg-staged, perm + convert) -> sm.ep.F
template<bool WRITEB>
__device__ __forceinline__ void compute_f32(SMu& sm, const float* __restrict__ W,
                                            const __half* __restrict__ hin, int n0)
{
    constexpr int BK = 64, LDS = 72;
    const int tid = threadIdx.x;
    const int w = tid >> 5, nf = w & 3, kh = w >> 2;
    const int niter = V / BK;   // 108

    wmma::fragment<wmma::accumulator, 16, 16, 16, float> acc;
    wmma::fill_fragment(acc, 0.0f);

    uint4 rb[2], ra;
    auto load = [&](int k0) {
#pragma unroll
        for (int p = 0; p < 2; p++) {
            int c = tid + p * 256;
            int row = c >> 3, kc = (c & 7) * 8;
            int nn = n0 + row;
            const float* s = W + ((size_t)(nn & 3) * V + (nn >> 2)) * V + k0 + kc;
            rb[p] = pack8(*(const float4*)s, *(const float4*)(s + 4));
            if constexpr (WRITEB)
                *(uint4*)(g_whh16 + (size_t)nn * V + k0 + kc) = rb[p];
        }
        if (tid < 128)
            ra = *(const uint4*)(hin + (size_t)(tid >> 3) * V + k0 + (tid & 7) * 8);
    };
    auto store = [&](int buf) {
#pragma unroll
        for (int p = 0; p < 2; p++) {
            int c = tid + p * 256;
            int row = c >> 3, kc = (c & 7) * 8;
            *(uint4*)(&sm.f.B[buf][row][kc]) = rb[p];
        }
        if (tid < 128)
            *(uint4*)(&sm.f.A[buf][tid >> 3][(tid & 7) * 8]) = ra;
    };

    load(0);
    store(0);
    load(BK);
    __syncthreads();

    for (int i = 0; i < niter; i++) {
        int p = i & 1;
        if (i + 1 < niter) store(p ^ 1);
        if (i + 2 < niter) load((i + 2) * BK);
        int kb = kh * 32;
#pragma unroll
        for (int kk = kb; kk < kb + 32; kk += 16) {
            wmma::fragment<wmma::matrix_a, 16, 16, 16, __half, wmma::row_major> af;
            wmma::fragment<wmma::matrix_b, 16, 16, 16, __half, wmma::col_major> bf;
            wmma::load_matrix_sync(af, &sm.f.A[p][0][kk], LDS);
            wmma::load_matrix_sync(bf, &sm.f.B[p][nf * 16][kk], LDS);
            wmma::mma_sync(acc, af, bf, acc);
        }
        __syncthreads();
    }

    wmma::store_matrix_sync(&sm.ep.R[w][0][0], acc, 32, wmma::mem_row_major);
    __syncthreads();
    combine8(sm.ep.R, sm.ep.F);
    __syncthreads();
}

__global__ __launch_bounds__(256, 3) void persist_kernel(
    const float* __restrict__ Whh_enc, const float* __restrict__ Whh_dec,
    const float* __restrict__ xrev,    const float* __restrict__ few,
    const float* __restrict__ Wfc,     const float* __restrict__ fcb,
    float* __restrict__ out)
{
    __shared__ __align__(16) SMu sm;

    const int tid   = threadIdx.x;
    const int n0    = blockIdx.x * 64;
    const int jbase = blockIdx.x * 16;
    const int eb  = tid >> 4, ejl = tid & 15;
    const int ejg = jbase + ejl;
    const int eidx = eb * V + ejg;

    unsigned nb = 0;
    float c_reg;

    // ---- step 0: h0 from xg (h=c=0) ----
    {
        float4 x4 = *(const float4*)&g_xg[(size_t)(eb * 8) * G4 + (size_t)ejg * 4];
        float4 bb = *(const float4*)&g_bep[ejg * 4];
        float i_ = sigf (x4.x + bb.x);
        float gg = tanhf(x4.z + bb.z);
        float o_ = sigf (x4.w + bb.w);
        c_reg = i_ * gg;
        g_h16[0][eidx] = __float2half(o_ * tanhf(c_reg));
    }
    grid_bar(++nb);

    // ---- steps 1..7 (fc_enc folded into t=7) ----
    for (int t = 1; t < TT; t++) {
        if (t == 1) compute_f32<true>(sm, Whh_enc, g_h16[0], n0);
        else        compute_f16(sm, g_h16[(t + 1) & 1], n0);

        {
            float4 pre = *(float4*)&sm.ep.F[eb][ejl * 4];
            float4 xg4 = *(const float4*)&g_xg[(size_t)(eb * 8 + t) * G4 + (size_t)ejg * 4];
            float4 bb  = *(const float4*)&g_bep[ejg * 4];
            float i_ = sigf (pre.x + xg4.x + bb.x);
            float f_ = sigf (pre.y + xg4.y + bb.y);
            float gg = tanhf(pre.z + xg4.z + bb.z);
            float o_ = sigf (pre.w + xg4.w + bb.w);
            c_reg = f_ * c_reg + i_ * gg;
            float h = o_ * tanhf(c_reg);
            g_h16[t & 1][eidx] = __float2half(h);
            if (t == TT - 1) {
                // fc_enc partial: 16-lane reduce, one atomicAdd per (block,b)
                float pe = h * few[ejg];
#pragma unroll
                for (int off = 8; off; off >>= 1)
                    pe += __shfl_xor_sync(0xffffffffu, pe, off);
                if (ejl == 0) atomicAdd(&out[eb], pe);
            }
        }
        grid_bar(++nb);
    }

    // ---- decoder (reads h7 = buf 1), writes g_hd16 ----
    compute_f32<false>(sm, Whh_dec, g_h16[1], n0);
    {
        float4 pre = *(float4*)&sm.ep.F[eb][ejl * 4];
        float4 bb  = *(const float4*)&g_bdp[ejg * 4];
        float4 ww  = *(const float4*)&g_widp[ejg * 4];
        float bi = pre.x + bb.x, bf_ = pre.y + bb.y;
        float bg = pre.z + bb.z, bo = pre.w + bb.w;
#pragma unroll
        for (int tr = 0; tr < TR; tr++) {
            float xr = xrev[eb * TR + tr];
            float i_ = sigf (bi + xr * ww.x);
            float f_ = sigf (bf_ + xr * ww.y);
            float gg = tanhf(bg + xr * ww.z);
            float o_ = sigf (bo + xr * ww.w);
            float cd = f_ * c_reg + i_ * gg;
            g_hd16[(size_t)(eb * TR + tr) * V + ejg] = __float2half(o_ * tanhf(cd));
        }
    }
    grid_bar(++nb);   // all of g_hd16 visible before fc_dec reads it

    // ---- fc_dec phase: block owns dec columns [bid*16, bid*16+16) ----
    {
        constexpr int BK = 64, LDS = 72;
        const int n0d = blockIdx.x * 16;
        const int w = tid >> 5, mf = w & 3, kh = w >> 2;
        const int niter = V / BK;   // 108

        wmma::fragment<wmma::accumulator, 16, 16, 16, float> acc;
        wmma::fill_fragment(acc, 0.0f);

        uint4 rbd, rad[2];
        auto load = [&](int k0) {
            if (tid < 128) {
                int row = tid >> 3, kc = (tid & 7) * 8;
                const float* s = Wfc + (size_t)(n0d + row) * V + k0 + kc;
                rbd = pack8(*(const float4*)s, *(const float4*)(s + 4));
            }
#pragma unroll
            for (int p = 0; p < 2; p++) {
                int c = tid + p * 256;
                int row = c >> 3, kc = (c & 7) * 8;
                rad[p] = *(const uint4*)(g_hd16 + (size_t)row * V + k0 + kc);
            }
        };
        auto store = [&](int buf) {
            if (tid < 128)
                *(uint4*)(&sm.d.B[buf][tid >> 3][(tid & 7) * 8]) = rbd;
#pragma unroll
            for (int p = 0; p < 2; p++) {
                int c = tid + p * 256;
                int row = c >> 3, kc = (c & 7) * 8;
                *(uint4*)(&sm.d.A[buf][row][kc]) = rad[p];
            }
        };

        load(0);
        store(0);
        load(BK);
        __syncthreads();

        for (int i = 0; i < niter; i++) {
            int p = i & 1;
            if (i + 1 < niter) store(p ^ 1);
            if (i + 2 < niter) load((i + 2) * BK);
            int kb = kh * 32;
#pragma unroll
            for (int kk = kb; kk < kb + 32; kk += 16) {
                wmma::fragment<wmma::matrix_a, 16, 16, 16, __half, wmma::row_major> af;
                wmma::fragment<wmma::matrix_b, 16, 16, 16, __half, wmma::col_major> bf;
                wmma::load_matrix_sync(af, &sm.d.A[p][mf * 16][kk], LDS);
                wmma::load_matrix_sync(bf, &sm.d.B[p][0][kk], LDS);
                wmma::mma_sync(acc, af, bf, acc);
            }
            __syncthreads();
        }

        wmma::store_matrix_sync(&sm.ep.R[w][0][0], acc, 32, wmma::mem_row_major);
        __syncthreads();

        // combine k-halves + bias + repeat(3) scatter, no intermediate buffer
        for (int c = tid; c < 64 * 16; c += 256) {
            int m = c >> 4, nl = c & 15;
            float val = sm.ep.R[m >> 4][m & 15][nl]
                      + sm.ep.R[(m >> 4) + 4][m & 15][nl]
                      + fcb[n0d + nl];
            int b = m >> 2, tr = m & 3;
            size_t base = 16 + (size_t)(b * 12 + tr * 3) * V + n0d + nl;
            out[base]         = val;
            out[base + V]     = val;
            out[base + 2 * V] = val;
        }
    }
}

// =====================================================================
extern "C" void kernel_launch(void* const* d_in, const int* in_sizes, int n_in,
                              void* d_out, int out_size)
{
    (void)in_sizes; (void)n_in; (void)out_size;
    const float* x        = (const float*)d_in[0];
    const float* x_rev    = (const float*)d_in[1];
    const float* W_ih_enc = (const float*)d_in[2];
    const float* W_hh_enc = (const float*)d_in[3];
    const float* b_enc    = (const float*)d_in[4];
    const float* fc_enc_w = (const float*)d_in[5];
    const float* fc_enc_b = (const float*)d_in[6];
    const float* W_ih_dec = (const float*)d_in[7];
    const float* W_hh_dec = (const float*)d_in[8];
    const float* b_dec    = (const float*)d_in[9];
    const float* fc_dec_w = (const float*)d_in[10];
    const float* fc_dec_b = (const float*)d_in[11];
    float* out = (float*)d_out;

    // 0) x -> fp16, permuted vectors, barrier reset, out[0..15] = bias
    prep_conv_kernel<<<540, 256>>>(x, b_enc, b_dec, W_ih_dec, fc_enc_b, out);

    // 1) xg = x @ W_ih_enc^T  (BK=32, full-K, direct store, 432 blocks)
    gemm_xg_kernel<<<dim3(G4 / 128, 2), 256>>>(W_ih_enc);

    // 2) persistent kernel: everything else
    persist_kernel<<<NBLK, 256>>>(W_hh_enc, W_hh_dec, x_rev,
                                  fc_enc_w, fc_dec_w, fc_dec_b, out);
}

// round 16
// speedup vs baseline: 1.0112x; 1.0112x over previous
#include <cuda_runtime.h>
#include <cuda_fp16.h>
#include <mma.h>
#include <cstddef>
#include <cstdint>

using namespace nvcuda;

#define V    6912
#define G4   27648   // 4*V
#define BSZ  16
#define TT   8
#define TR   4
#define NBLK 432     // persistent grid size

// ---------------- device scratch (no allocation allowed) ----------------
// Gate-interleaved layouts: index n' = j*4 + g  (g: 0=i,1=f,2=g,3=o)
__device__ __half g_whh16[(size_t)G4 * V];   // fp16 W_hh_enc, rows interleaved
__device__ __half g_x16 [128 * V];           // x fp16
__device__ __half g_h16 [2][BSZ * V];        // encoder h fp16, ping-pong
__device__ __half g_hd16[BSZ * TR * V];      // decoder h_d (fp16, fc_dec A)
__device__ float  g_xg  [128 * G4];          // xg, cols interleaved
__device__ float  g_dec [BSZ * TR * V];      // fc_dec accumulator (atomic)
__device__ float  g_bep [G4];                // b_enc permuted
__device__ float  g_bdp [G4];                // b_dec permuted
__device__ float  g_widp[G4];                // W_ih_dec permuted
__device__ unsigned g_bar;                   // persistent-kernel barrier counter

__device__ __forceinline__ float sigf(float x) { return 1.0f / (1.0f + expf(-x)); }

__device__ __forceinline__ uint4 pack8(float4 a, float4 b)
{
    __half2 h0 = __floats2half2_rn(a.x, a.y);
    __half2 h1 = __floats2half2_rn(a.z, a.w);
    __half2 h2 = __floats2half2_rn(b.x, b.y);
    __half2 h3 = __floats2half2_rn(b.z, b.w);
    uint4 u;
    u.x = *reinterpret_cast<unsigned*>(&h0);
    u.y = *reinterpret_cast<unsigned*>(&h1);
    u.z = *reinterpret_cast<unsigned*>(&h2);
    u.w = *reinterpret_cast<unsigned*>(&h3);
    return u;
}

// =====================================================================
// Prologue: blocks [0,432): x -> fp16; [432,540): permute b/W vectors;
// resets grid barrier; seeds out[0..15] with fc_enc bias.
// =====================================================================
__global__ void prep_conv_kernel(const float* __restrict__ x,
                                 const float* __restrict__ be,
                                 const float* __restrict__ bd,
                                 const float* __restrict__ wid,
                                 const float* __restrict__ feb,
                                 float* __restrict__ out)
{
    if (blockIdx.x == 0 && threadIdx.x == 0) g_bar = 0u;
    int bx = blockIdx.x;
    if (bx < 432) {
        int idx = bx * 256 + threadIdx.x;           // 432*256 = 128*V/8
        const float4* s = (const float4*)x + (size_t)idx * 2;
        ((uint4*)g_x16)[idx] = pack8(s[0], s[1]);
    } else {
        int idx = (bx - 432) * 256 + threadIdx.x;   // 108*256 = G4
        int src = (idx & 3) * V + (idx >> 2);
        g_bep[idx]  = be[src];
        g_bdp[idx]  = bd[src];
        g_widp[idx] = wid[src];
        if (bx == 539 && threadIdx.x < BSZ) out[threadIdx.x] = feb[0];
    }
}

// =====================================================================
// xg GEMM: BM=64 (grid.y = m-half), BN=128, BK=32, full K, direct store.
// =====================================================================
__global__ __launch_bounds__(256) void gemm_xg_kernel(const float* __restrict__ Wih)
{
    constexpr int BK = 32, BNB = 128, LDS = BK + 8;
    __shared__ __align__(16) __half sA[2][64][LDS];
    __shared__ __align__(16) __half sB[2][BNB][LDS];

    const int tid = threadIdx.x;
    const int n0  = blockIdx.x * BNB;
    const int m0  = blockIdx.y * 64;

    const int w  = tid >> 5;
    const int wm = w >> 2, wn = w & 3;

    wmma::fragment<wmma::accumulator, 16, 16, 16, float> acc[2][2];
#pragma unroll
    for (int i = 0; i < 2; i++)
#pragma unroll
        for (int j = 0; j < 2; j++) wmma::fill_fragment(acc[i][j], 0.0f);

    uint4 rb[2], ra;
    auto load = [&](int k0) {
#pragma unroll
        for (int p = 0; p < 2; p++) {
            int c = tid + p * 256;
            int row = c >> 2, kc = (c & 3) * 8;
            int nn = n0 + row;
            const float* s = Wih + ((size_t)(nn & 3) * V + (nn >> 2)) * V + k0 + kc;
            rb[p] = pack8(*(const float4*)s, *(const float4*)(s + 4));
        }
        {
            int row = tid >> 2, kc = (tid & 3) * 8;
            ra = *(const uint4*)(g_x16 + (size_t)(m0 + row) * V + k0 + kc);
        }
    };
    auto store = [&](int buf) {
#pragma unroll
        for (int p = 0; p < 2; p++) {
            int c = tid + p * 256;
            int row = c >> 2, kc = (c & 3) * 8;
            *(uint4*)(&sB[buf][row][kc]) = rb[p];
        }
        *(uint4*)(&sA[buf][tid >> 2][(tid & 3) * 8]) = ra;
    };

    load(0);
    store(0);
    load(BK);
    __syncthreads();

    const int niter = V / BK;   // 216
    for (int i = 0; i < niter; i++) {
        int p = i & 1;
        if (i + 1 < niter) store(p ^ 1);
        if (i + 2 < niter) load((i + 2) * BK);
#pragma unroll
        for (int kk = 0; kk < BK; kk += 16) {
            wmma::fragment<wmma::matrix_a, 16, 16, 16, __half, wmma::row_major> af[2];
            wmma::fragment<wmma::matrix_b, 16, 16, 16, __half, wmma::col_major> bf[2];
#pragma unroll
            for (int i_ = 0; i_ < 2; i_++)
                wmma::load_matrix_sync(af[i_], &sA[p][wm * 32 + i_ * 16][kk], LDS);
#pragma unroll
            for (int j_ = 0; j_ < 2; j_++)
                wmma::load_matrix_sync(bf[j_], &sB[p][wn * 32 + j_ * 16][kk], LDS);
#pragma unroll
            for (int i_ = 0; i_ < 2; i_++)
#pragma unroll
                for (int j_ = 0; j_ < 2; j_++)
                    wmma::mma_sync(acc[i_][j_], af[i_], bf[j_], acc[i_][j_]);
        }
        __syncthreads();
    }

#pragma unroll
    for (int i_ = 0; i_ < 2; i_++)
#pragma unroll
        for (int j_ = 0; j_ < 2; j_++)
            wmma::store_matrix_sync(
                g_xg + (size_t)(m0 + wm * 32 + i_ * 16) * G4 + n0 + wn * 32 + j_ * 16,
                acc[i_][j_], G4, wmma::mem_row_major);
}

// =====================================================================
// Persistent kernel: step0 + steps 1..7 (+fc_enc fold) + decoder.
// Grid 432, guaranteed 3 blocks/SM.
// =====================================================================
struct SMu {
    union {
        struct { __half A[3][16][136]; __half B[3][64][136]; } h;   // fp16 rec
        struct { __half A[2][16][72];  __half B[2][64][72];  } f;   // fp32 rec
        struct { float R[8][16][32]; float F[16][64]; } ep;          // epilogues
    };
};

__device__ __forceinline__ void grid_bar(unsigned k)
{
    __threadfence();
    __syncthreads();
    if (threadIdx.x == 0) {
        atomicAdd(&g_bar, 1u);
        volatile unsigned* p = &g_bar;
        while (*p < k * (unsigned)NBLK) { }
    }
    __syncthreads();
}

__device__ __forceinline__ void combine8(float (*sR)[16][32], float (*sF)[64])
{
    int tid = threadIdx.x;
    for (int c = tid; c < 16 * 64; c += 256) {
        int m = c >> 6, n = c & 63;
        int f = n >> 4, cc = n & 15;
        sF[m][n] = sR[f][m][cc] + sR[f + 4][m][cc];
    }
}

// fp16-weight mainloop (BK=128, 3-stage cp.async) -> sm.ep.F
__device__ __forceinline__ void compute_f16(SMu& sm, const __half* __restrict__ hin,
                                            int n0)
{
    constexpr int BK = 128, STAGES = 3, LDS = 136;
    const int tid = threadIdx.x;
    const int w = tid >> 5, nf = w & 3, kh = w >> 2;
    const int niter = V / BK;   // 54

    wmma::fragment<wmma::accumulator, 16, 16, 16, float> acc;
    wmma::fill_fragment(acc, 0.0f);

    auto stage = [&](int s, int k0) {
#pragma unroll
        for (int p = 0; p < 4; p++) {
            int c = tid + p * 256;
            int row = c >> 4, kc = (c & 15) * 8;
            uint32_t d = (uint32_t)__cvta_generic_to_shared(&sm.h.B[s][row][kc]);
            const void* g = g_whh16 + (size_t)(n0 + row) * V + k0 + kc;
            asm volatile("cp.async.cg.shared.global [%0], [%1], 16;\n" :: "r"(d), "l"(g));
        }
        {
            int row = tid >> 4, kc = (tid & 15) * 8;
            uint32_t d = (uint32_t)__cvta_generic_to_shared(&sm.h.A[s][row][kc]);
            const void* g = hin + (size_t)row * V + k0 + kc;
            asm volatile("cp.async.cg.shared.global [%0], [%1], 16;\n" :: "r"(d), "l"(g));
        }
        asm volatile("cp.async.commit_group;\n");
    };

    int issued = 0;
    for (; issued < STAGES - 1; issued++) stage(issued, issued * BK);

    for (int i = 0; i < niter; i++) {
        asm volatile("cp.async.wait_group %0;\n" :: "n"(STAGES - 2));
        __syncthreads();
        if (issued < niter) { stage(issued % STAGES, issued * BK); issued++; }
        else                { asm volatile("cp.async.commit_group;\n"); }
        int s = i % STAGES;
        int kb = kh * 64;
#pragma unroll
        for (int kk = kb; kk < kb + 64; kk += 16) {
            wmma::fragment<wmma::matrix_a, 16, 16, 16, __half, wmma::row_major> af;
            wmma::fragment<wmma::matrix_b, 16, 16, 16, __half, wmma::col_major> bf;
            wmma::load_matrix_sync(af, &sm.h.A[s][0][kk], LDS);
            wmma::load_matrix_sync(bf, &sm.h.B[s][nf * 16][kk], LDS);
            wmma::mma_sync(acc, af, bf, acc);
        }
    }
    asm volatile("cp.async.wait_group 0;\n");
    __syncthreads();
    wmma::store_matrix_sync(&sm.ep.R[w][0][0], acc, 32, wmma::mem_row_major);
    __syncthreads();
    combine8(sm.ep.R, sm.ep.F);
    __syncthreads();
}

// fp32-weight mainloop (BK=64, reg-staged, perm + convert) -> sm.ep.F
template<bool WRITEB>
__device__ __forceinline__ void compute_f32(SMu& sm, const float* __restrict__ W,
                                            const __half* __restrict__ hin, int n0)
{
    constexpr int BK = 64, LDS = 72;
    const int tid = threadIdx.x;
    const int w = tid >> 5, nf = w & 3, kh = w >> 2;
    const int niter = V / BK;   // 108

    wmma::fragment<wmma::accumulator, 16, 16, 16, float> acc;
    wmma::fill_fragment(acc, 0.0f);

    uint4 rb[2], ra;
    auto load = [&](int k0) {
#pragma unroll
        for (int p = 0; p < 2; p++) {
            int c = tid + p * 256;
            int row = c >> 3, kc = (c & 7) * 8;
            int nn = n0 + row;
            const float* s = W + ((size_t)(nn & 3) * V + (nn >> 2)) * V + k0 + kc;
            rb[p] = pack8(*(const float4*)s, *(const float4*)(s + 4));
            if constexpr (WRITEB)
                *(uint4*)(g_whh16 + (size_t)nn * V + k0 + kc) = rb[p];
        }
        if (tid < 128)
            ra = *(const uint4*)(hin + (size_t)(tid >> 3) * V + k0 + (tid & 7) * 8);
    };
    auto store = [&](int buf) {
#pragma unroll
        for (int p = 0; p < 2; p++) {
            int c = tid + p * 256;
            int row = c >> 3, kc = (c & 7) * 8;
            *(uint4*)(&sm.f.B[buf][row][kc]) = rb[p];
        }
        if (tid < 128)
            *(uint4*)(&sm.f.A[buf][tid >> 3][(tid & 7) * 8]) = ra;
    };

    load(0);
    store(0);
    load(BK);
    __syncthreads();

    for (int i = 0; i < niter; i++) {
        int p = i & 1;
        if (i + 1 < niter) store(p ^ 1);
        if (i + 2 < niter) load((i + 2) * BK);
        int kb = kh * 32;
#pragma unroll
        for (int kk = kb; kk < kb + 32; kk += 16) {
            wmma::fragment<wmma::matrix_a, 16, 16, 16, __half, wmma::row_major> af;
            wmma::fragment<wmma::matrix_b, 16, 16, 16, __half, wmma::col_major> bf;
            wmma::load_matrix_sync(af, &sm.f.A[p][0][kk], LDS);
            wmma::load_matrix_sync(bf, &sm.f.B[p][nf * 16][kk], LDS);
            wmma::mma_sync(acc, af, bf, acc);
        }
        __syncthreads();
    }

    wmma::store_matrix_sync(&sm.ep.R[w][0][0], acc, 32, wmma::mem_row_major);
    __syncthreads();
    combine8(sm.ep.R, sm.ep.F);
    __syncthreads();
}

__global__ __launch_bounds__(256, 3) void persist_kernel(
    const float* __restrict__ Whh_enc, const float* __restrict__ Whh_dec,
    const float* __restrict__ xrev,    const float* __restrict__ few,
    float* __restrict__ out)
{
    __shared__ __align__(16) SMu sm;

    const int tid   = threadIdx.x;
    const int n0    = blockIdx.x * 64;
    const int jbase = blockIdx.x * 16;
    const int eb  = tid >> 4, ejl = tid & 15;
    const int ejg = jbase + ejl;
    const int eidx = eb * V + ejg;

    unsigned nb = 0;
    float c_reg;

    // ---- step 0: h0 from xg (h=c=0) ----
    {
        float4 x4 = *(const float4*)&g_xg[(size_t)(eb * 8) * G4 + (size_t)ejg * 4];
        float4 bb = *(const float4*)&g_bep[ejg * 4];
        float i_ = sigf (x4.x + bb.x);
        float gg = tanhf(x4.z + bb.z);
        float o_ = sigf (x4.w + bb.w);
        c_reg = i_ * gg;
        g_h16[0][eidx] = __float2half(o_ * tanhf(c_reg));
    }
    grid_bar(++nb);

    // ---- steps 1..7 (fc_enc folded into t=7 via register h) ----
    for (int t = 1; t < TT; t++) {
        if (t == 1) compute_f32<true>(sm, Whh_enc, g_h16[0], n0);
        else        compute_f16(sm, g_h16[(t + 1) & 1], n0);

        {
            float4 pre = *(float4*)&sm.ep.F[eb][ejl * 4];
            float4 xg4 = *(const float4*)&g_xg[(size_t)(eb * 8 + t) * G4 + (size_t)ejg * 4];
            float4 bb  = *(const float4*)&g_bep[ejg * 4];
            float i_ = sigf (pre.x + xg4.x + bb.x);
            float f_ = sigf (pre.y + xg4.y + bb.y);
            float gg = tanhf(pre.z + xg4.z + bb.z);
            float o_ = sigf (pre.w + xg4.w + bb.w);
            c_reg = f_ * c_reg + i_ * gg;
            float h = o_ * tanhf(c_reg);
            g_h16[t & 1][eidx] = __float2half(h);
            if (t == TT - 1) {
                // fc_enc partial: 16-lane reduce, one atomicAdd per half-warp
                float pe = h * few[ejg];
#pragma unroll
                for (int off = 8; off; off >>= 1)
                    pe += __shfl_xor_sync(0xffffffffu, pe, off);
                if (ejl == 0) atomicAdd(&out[eb], pe);
            }
        }
        grid_bar(++nb);
    }

    // ---- decoder (reads h7 = buf 1), writes g_hd16 + zeroes g_dec ----
    compute_f32<false>(sm, Whh_dec, g_h16[1], n0);
    {
        float4 pre = *(float4*)&sm.ep.F[eb][ejl * 4];
        float4 bb  = *(const float4*)&g_bdp[ejg * 4];
        float4 ww  = *(const float4*)&g_widp[ejg * 4];
        float bi = pre.x + bb.x, bf_ = pre.y + bb.y;
        float bg = pre.z + bb.z, bo = pre.w + bb.w;
#pragma unroll
        for (int tr = 0; tr < TR; tr++) {
            float xr = xrev[eb * TR + tr];
            float i_ = sigf (bi + xr * ww.x);
            float f_ = sigf (bf_ + xr * ww.y);
            float gg = tanhf(bg + xr * ww.z);
            float o_ = sigf (bo + xr * ww.w);
            float cd = f_ * c_reg + i_ * gg;
            size_t o = (size_t)(eb * TR + tr) * V + ejg;
            g_hd16[o] = __float2half(o_ * tanhf(cd));
            g_dec[o]  = 0.f;                 // pre-zero for fc_dec atomics
        }
    }
}

// =====================================================================
// fc_dec GEMM: BM=64 rows of hd, K-split 4, atomic-reduce into g_dec.
// =====================================================================
__global__ __launch_bounds__(256)
void gemm_fcdec(const __half* __restrict__ A, const float* __restrict__ Bf,
                float* __restrict__ C, int N, int klen)
{
    constexpr int BM = 64, BK = 32, BNB = 128, LDS = BK + 8;
    __shared__ __align__(16) __half sA[2][BM][LDS];
    __shared__ __align__(16) __half sB[2][BNB][LDS];
    __shared__ __align__(16) float  sC[BM][BNB + 4];

    const int tid   = threadIdx.x;
    const int n0    = blockIdx.x * BNB;
    const int kbase = blockIdx.y * klen;
    const int niter = klen / BK;

    const int w  = tid >> 5;
    const int wm = w >> 2, wn = w & 3;

    wmma::fragment<wmma::accumulator, 16, 16, 16, float> acc[2][2];
#pragma unroll
    for (int i = 0; i < 2; i++)
#pragma unroll
        for (int j = 0; j < 2; j++) wmma::fill_fragment(acc[i][j], 0.0f);

    uint4 rb[2], ra;
    auto load = [&](int k0) {
#pragma unroll
        for (int p = 0; p < 2; p++) {
            int c = tid + p * 256;
            int row = c >> 2, kc = (c & 3) * 8;
            const float* s = Bf + (size_t)(n0 + row) * V + k0 + kc;
            rb[p] = pack8(*(const float4*)s, *(const float4*)(s + 4));
        }
        ra = *(const uint4*)(A + (size_t)(tid >> 2) * V + k0 + (tid & 3) * 8);
    };
    auto store = [&](int buf) {
#pragma unroll
        for (int p = 0; p < 2; p++) {
            int c = tid + p * 256;
            int row = c >> 2, kc = (c & 3) * 8;
            *(uint4*)(&sB[buf][row][kc]) = rb[p];
        }
        *(uint4*)(&sA[buf][tid >> 2][(tid & 3) * 8]) = ra;
    };

    load(kbase);
    store(0);
    if (niter > 1) load(kbase + BK);
    __syncthreads();

    for (int i = 0; i < niter; i++) {
        int p = i & 1;
        if (i + 1 < niter) store(p ^ 1);
        if (i + 2 < niter) load(kbase + (i + 2) * BK);
#pragma unroll
        for (int kk = 0; kk < BK; kk += 16) {
            wmma::fragment<wmma::matrix_a, 16, 16, 16, __half, wmma::row_major> af[2];
            wmma::fragment<wmma::matrix_b, 16, 16, 16, __half, wmma::col_major> bf[2];
#pragma unroll
            for (int i_ = 0; i_ < 2; i_++)
                wmma::load_matrix_sync(af[i_], &sA[p][wm * 32 + i_ * 16][kk], LDS);
#pragma unroll
            for (int j_ = 0; j_ < 2; j_++)
                wmma::load_matrix_sync(bf[j_], &sB[p][wn * 32 + j_ * 16][kk], LDS);
#pragma unroll
            for (int i_ = 0; i_ < 2; i_++)
#pragma unroll
                for (int j_ = 0; j_ < 2; j_++)
                    wmma::mma_sync(acc[i_][j_], af[i_], bf[j_], acc[i_][j_]);
        }
        __syncthreads();
    }

#pragma unroll
    for (int i_ = 0; i_ < 2; i_++)
#pragma unroll
        for (int j_ = 0; j_ < 2; j_++)
            wmma::store_matrix_sync(&sC[wm * 32 + i_ * 16][wn * 32 + j_ * 16],
                                    acc[i_][j_], BNB + 4, wmma::mem_row_major);
    __syncthreads();
    for (int c = tid; c < BM * BNB; c += 256) {
        int m = c / BNB, n = c - m * BNB;
        atomicAdd(&C[(size_t)m * N + n0 + n], sC[m][n]);
    }
}

// =====================================================================
__global__ void dec_out_kernel(const float* __restrict__ fcb,
                               float* __restrict__ out)
{
    int idx = blockIdx.x * 256 + threadIdx.x;   // 64*V exactly
    int m = idx / V, n = idx - m * V;
    float val = g_dec[idx] + fcb[n];
    int b = m >> 2, tr = m & 3;
    size_t base = 16 + (size_t)(b * 12 + tr * 3) * V + n;
    out[base]         = val;
    out[base + V]     = val;
    out[base + 2 * V] = val;
}

// =====================================================================
extern "C" void kernel_launch(void* const* d_in, const int* in_sizes, int n_in,
                              void* d_out, int out_size)
{
    (void)in_sizes; (void)n_in; (void)out_size;
    const float* x        = (const float*)d_in[0];
    const float* x_rev    = (const float*)d_in[1];
    const float* W_ih_enc = (const float*)d_in[2];
    const float* W_hh_enc = (const float*)d_in[3];
    const float* b_enc    = (const float*)d_in[4];
    const float* fc_enc_w = (const float*)d_in[5];
    const float* fc_enc_b = (const float*)d_in[6];
    const float* W_ih_dec = (const float*)d_in[7];
    const float* W_hh_dec = (const float*)d_in[8];
    const float* b_dec    = (const float*)d_in[9];
    const float* fc_dec_w = (const float*)d_in[10];
    const float* fc_dec_b = (const float*)d_in[11];
    float* out = (float*)d_out;

    __half* hd16_p; float* dec_p;
    cudaGetSymbolAddress((void**)&hd16_p, g_hd16);
    cudaGetSymbolAddress((void**)&dec_p,  g_dec);

    // 0) x -> fp16, permuted vectors, barrier reset, out[0..15] = bias
    prep_conv_kernel<<<540, 256>>>(x, b_enc, b_dec, W_ih_dec, fc_enc_b, out);

    // 1) xg = x @ W_ih_enc^T  (BK=32, full-K, direct store, 432 blocks)
    gemm_xg_kernel<<<dim3(G4 / 128, 2), 256>>>(W_ih_enc);

    // 2) persistent kernel: step0 + steps 1..7 (+fc_enc) + decoder
    persist_kernel<<<NBLK, 256>>>(W_hh_enc, W_hh_dec, x_rev, fc_enc_w, out);

    // 3) dec += h_d @ fc_dec_w^T (ksplit 4, atomic), bias + repeat(3) scatter
    gemm_fcdec<<<dim3(V / 128, 4), 256>>>(hd16_p, fc_dec_w, dec_p, V, V / 4);
    dec_out_kernel<<<BSZ * TR * V / 256, 256>>>(fc_dec_b, out);
}

// round 17
// speedup vs baseline: 1.0407x; 1.0291x over previous
#include <cuda_runtime.h>
#include <cuda_fp16.h>
#include <mma.h>
#include <cstddef>
#include <cstdint>

using namespace nvcuda;

#define V    6912
#define G4   27648   // 4*V
#define BSZ  16
#define TT   8
#define TR   4
#define NBLK 432     // persistent grid size

// ---------------- device scratch (no allocation allowed) ----------------
// Gate-interleaved layouts: index n' = j*4 + g  (g: 0=i,1=f,2=g,3=o)
__device__ __half g_whh16[(size_t)G4 * V];   // fp16 W_hh_enc, rows interleaved
__device__ __half g_x16 [128 * V];           // x fp16
__device__ __half g_h16 [2][BSZ * V];        // encoder h fp16, ping-pong
__device__ __half g_hd16[BSZ * TR * V];      // decoder h_d (fp16, fc_dec A)
__device__ float  g_xg  [128 * G4];          // xg, cols interleaved
__device__ float  g_dec [BSZ * TR * V];      // fc_dec accumulator (atomic)
__device__ float  g_bep [G4];                // b_enc permuted
__device__ float  g_bdp [G4];                // b_dec permuted
__device__ float  g_widp[G4];                // W_ih_dec permuted
__device__ unsigned g_bar;                   // persistent-kernel barrier counter

__device__ __forceinline__ float sigf(float x) { return 1.0f / (1.0f + expf(-x)); }

__device__ __forceinline__ uint4 pack8(float4 a, float4 b)
{
    __half2 h0 = __floats2half2_rn(a.x, a.y);
    __half2 h1 = __floats2half2_rn(a.z, a.w);
    __half2 h2 = __floats2half2_rn(b.x, b.y);
    __half2 h3 = __floats2half2_rn(b.z, b.w);
    uint4 u;
    u.x = *reinterpret_cast<unsigned*>(&h0);
    u.y = *reinterpret_cast<unsigned*>(&h1);
    u.z = *reinterpret_cast<unsigned*>(&h2);
    u.w = *reinterpret_cast<unsigned*>(&h3);
    return u;
}

// =====================================================================
// Prologue: blocks [0,432): x -> fp16; [432,540): permute b/W vectors;
// resets grid barrier; seeds out[0..15] with fc_enc bias.
// =====================================================================
__global__ void prep_conv_kernel(const float* __restrict__ x,
                                 const float* __restrict__ be,
                                 const float* __restrict__ bd,
                                 const float* __restrict__ wid,
                                 const float* __restrict__ feb,
                                 float* __restrict__ out)
{
    if (blockIdx.x == 0 && threadIdx.x == 0) g_bar = 0u;
    int bx = blockIdx.x;
    if (bx < 432) {
        int idx = bx * 256 + threadIdx.x;           // 432*256 = 128*V/8
        const float4* s = (const float4*)x + (size_t)idx * 2;
        ((uint4*)g_x16)[idx] = pack8(s[0], s[1]);
    } else {
        int idx = (bx - 432) * 256 + threadIdx.x;   // 108*256 = G4
        int src = (idx & 3) * V + (idx >> 2);
        g_bep[idx]  = be[src];
        g_bdp[idx]  = bd[src];
        g_widp[idx] = wid[src];
        if (bx == 539 && threadIdx.x < BSZ) out[threadIdx.x] = feb[0];
    }
}

// =====================================================================
// xg GEMM: BM=64 (grid.y = m-half), BN=128, BK=32, full K, direct store.
// =====================================================================
__global__ __launch_bounds__(256) void gemm_xg_kernel(const float* __restrict__ Wih)
{
    constexpr int BK = 32, BNB = 128, LDS = BK + 8;
    __shared__ __align__(16) __half sA[2][64][LDS];
    __shared__ __align__(16) __half sB[2][BNB][LDS];

    const int tid = threadIdx.x;
    const int n0  = blockIdx.x * BNB;
    const int m0  = blockIdx.y * 64;

    const int w  = tid >> 5;
    const int wm = w >> 2, wn = w & 3;

    wmma::fragment<wmma::accumulator, 16, 16, 16, float> acc[2][2];
#pragma unroll
    for (int i = 0; i < 2; i++)
#pragma unroll
        for (int j = 0; j < 2; j++) wmma::fill_fragment(acc[i][j], 0.0f);

    uint4 rb[2], ra;
    auto load = [&](int k0) {
#pragma unroll
        for (int p = 0; p < 2; p++) {
            int c = tid + p * 256;
            int row = c >> 2, kc = (c & 3) * 8;
            int nn = n0 + row;
            const float* s = Wih + ((size_t)(nn & 3) * V + (nn >> 2)) * V + k0 + kc;
            rb[p] = pack8(*(const float4*)s, *(const float4*)(s + 4));
        }
        {
            int row = tid >> 2, kc = (tid & 3) * 8;
            ra = *(const uint4*)(g_x16 + (size_t)(m0 + row) * V + k0 + kc);
        }
    };
    auto store = [&](int buf) {
#pragma unroll
        for (int p = 0; p < 2; p++) {
            int c = tid + p * 256;
            int row = c >> 2, kc = (c & 3) * 8;
            *(uint4*)(&sB[buf][row][kc]) = rb[p];
        }
        *(uint4*)(&sA[buf][tid >> 2][(tid & 3) * 8]) = ra;
    };

    load(0);
    store(0);
    load(BK);
    __syncthreads();

    const int niter = V / BK;   // 216
    for (int i = 0; i < niter; i++) {
        int p = i & 1;
        if (i + 1 < niter) store(p ^ 1);
        if (i + 2 < niter) load((i + 2) * BK);
#pragma unroll
        for (int kk = 0; kk < BK; kk += 16) {
            wmma::fragment<wmma::matrix_a, 16, 16, 16, __half, wmma::row_major> af[2];
            wmma::fragment<wmma::matrix_b, 16, 16, 16, __half, wmma::col_major> bf[2];
#pragma unroll
            for (int i_ = 0; i_ < 2; i_++)
                wmma::load_matrix_sync(af[i_], &sA[p][wm * 32 + i_ * 16][kk], LDS);
#pragma unroll
            for (int j_ = 0; j_ < 2; j_++)
                wmma::load_matrix_sync(bf[j_], &sB[p][wn * 32 + j_ * 16][kk], LDS);
#pragma unroll
            for (int i_ = 0; i_ < 2; i_++)
#pragma unroll
                for (int j_ = 0; j_ < 2; j_++)
                    wmma::mma_sync(acc[i_][j_], af[i_], bf[j_], acc[i_][j_]);
        }
        __syncthreads();
    }

#pragma unroll
    for (int i_ = 0; i_ < 2; i_++)
#pragma unroll
        for (int j_ = 0; j_ < 2; j_++)
            wmma::store_matrix_sync(
                g_xg + (size_t)(m0 + wm * 32 + i_ * 16) * G4 + n0 + wn * 32 + j_ * 16,
                acc[i_][j_], G4, wmma::mem_row_major);
}

// =====================================================================
// Persistent kernel: step0 + steps 1..7 (+fc_enc fold) + decoder.
// Grid 432, guaranteed 3 blocks/SM.
// =====================================================================
struct SMu {
    union {
        struct { __half A[3][16][136]; __half B[3][64][136]; } h;   // fp16 rec
        struct { __half A[2][16][72];  __half B[2][64][72];  } f;   // fp32 rec
        struct { float R[8][16][32]; float F[16][64]; } ep;          // epilogues
    };
};

__device__ __forceinline__ void grid_bar(unsigned k)
{
    __threadfence();
    __syncthreads();
    if (threadIdx.x == 0) {
        atomicAdd(&g_bar, 1u);
        volatile unsigned* p = &g_bar;
        while (*p < k * (unsigned)NBLK) { }
    }
    __syncthreads();
}

__device__ __forceinline__ void combine8(float (*sR)[16][32], float (*sF)[64])
{
    int tid = threadIdx.x;
    for (int c = tid; c < 16 * 64; c += 256) {
        int m = c >> 6, n = c & 63;
        int f = n >> 4, cc = n & 15;
        sF[m][n] = sR[f][m][cc] + sR[f + 4][m][cc];
    }
}

// fp16-weight mainloop (BK=128, 3-stage cp.async) -> sm.ep.F
__device__ __forceinline__ void compute_f16(SMu& sm, const __half* __restrict__ hin,
                                            int n0)
{
    constexpr int BK = 128, STAGES = 3, LDS = 136;
    const int tid = threadIdx.x;
    const int w = tid >> 5, nf = w & 3, kh = w >> 2;
    const int niter = V / BK;   // 54

    wmma::fragment<wmma::accumulator, 16, 16, 16, float> acc;
    wmma::fill_fragment(acc, 0.0f);

    auto stage = [&](int s, int k0) {
#pragma unroll
        for (int p = 0; p < 4; p++) {
            int c = tid + p * 256;
            int row = c >> 4, kc = (c & 15) * 8;
            uint32_t d = (uint32_t)__cvta_generic_to_shared(&sm.h.B[s][row][kc]);
            const void* g = g_whh16 + (size_t)(n0 + row) * V + k0 + kc;
            asm volatile("cp.async.cg.shared.global [%0], [%1], 16;\n" :: "r"(d), "l"(g));
        }
        {
            int row = tid >> 4, kc = (tid & 15) * 8;
            uint32_t d = (uint32_t)__cvta_generic_to_shared(&sm.h.A[s][row][kc]);
            const void* g = hin + (size_t)row * V + k0 + kc;
            asm volatile("cp.async.cg.shared.global [%0], [%1], 16;\n" :: "r"(d), "l"(g));
        }
        asm volatile("cp.async.commit_group;\n");
    };

    int issued = 0;
    for (; issued < STAGES - 1; issued++) stage(issued, issued * BK);

    for (int i = 0; i < niter; i++) {
        asm volatile("cp.async.wait_group %0;\n" :: "n"(STAGES - 2));
        __syncthreads();
        if (issued < niter) { stage(issued % STAGES, issued * BK); issued++; }
        else                { asm volatile("cp.async.commit_group;\n"); }
        int s = i % STAGES;
        int kb = kh * 64;
#pragma unroll
        for (int kk = kb; kk < kb + 64; kk += 16) {
            wmma::fragment<wmma::matrix_a, 16, 16, 16, __half, wmma::row_major> af;
            wmma::fragment<wmma::matrix_b, 16, 16, 16, __half, wmma::col_major> bf;
            wmma::load_matrix_sync(af, &sm.h.A[s][0][kk], LDS);
            wmma::load_matrix_sync(bf, &sm.h.B[s][nf * 16][kk], LDS);
            wmma::mma_sync(acc, af, bf, acc);
        }
    }
    asm volatile("cp.async.wait_group 0;\n");
    __syncthreads();
    wmma::store_matrix_sync(&sm.ep.R[w][0][0], acc, 32, wmma::mem_row_major);
    __syncthreads();
    combine8(sm.ep.R, sm.ep.F);
    __syncthreads();
}

// fp32-weight mainloop (BK=64, reg-staged, perm + convert) -> sm.ep.F
template<bool WRITEB>
__device__ __forceinline__ void compute_f32(SMu& sm, const float* __restrict__ W,
                                            const __half* __restrict__ hin, int n0)
{
    constexpr int BK = 64, LDS = 72;
    const int tid = threadIdx.x;
    const int w = tid >> 5, nf = w & 3, kh = w >> 2;
    const int niter = V / BK;   // 108

    wmma::fragment<wmma::accumulator, 16, 16, 16, float> acc;
    wmma::fill_fragment(acc, 0.0f);

    uint4 rb[2], ra;
    auto load = [&](int k0) {
#pragma unroll
        for (int p = 0; p < 2; p++) {
            int c = tid + p * 256;
            int row = c >> 3, kc = (c & 7) * 8;
            int nn = n0 + row;
            const float* s = W + ((size_t)(nn & 3) * V + (nn >> 2)) * V + k0 + kc;
            rb[p] = pack8(*(const float4*)s, *(const float4*)(s + 4));
            if constexpr (WRITEB)
                *(uint4*)(g_whh16 + (size_t)nn * V + k0 + kc) = rb[p];
        }
        if (tid < 128)
            ra = *(const uint4*)(hin + (size_t)(tid >> 3) * V + k0 + (tid & 7) * 8);
    };
    auto store = [&](int buf) {
#pragma unroll
        for (int p = 0; p < 2; p++) {
            int c = tid + p * 256;
            int row = c >> 3, kc = (c & 7) * 8;
            *(uint4*)(&sm.f.B[buf][row][kc]) = rb[p];
        }
        if (tid < 128)
            *(uint4*)(&sm.f.A[buf][tid >> 3][(tid & 7) * 8]) = ra;
    };

    load(0);
    store(0);
    load(BK);
    __syncthreads();

    for (int i = 0; i < niter; i++) {
        int p = i & 1;
        if (i + 1 < niter) store(p ^ 1);
        if (i + 2 < niter) load((i + 2) * BK);
        int kb = kh * 32;
#pragma unroll
        for (int kk = kb; kk < kb + 32; kk += 16) {
            wmma::fragment<wmma::matrix_a, 16, 16, 16, __half, wmma::row_major> af;
            wmma::fragment<wmma::matrix_b, 16, 16, 16, __half, wmma::col_major> bf;
            wmma::load_matrix_sync(af, &sm.f.A[p][0][kk], LDS);
            wmma::load_matrix_sync(bf, &sm.f.B[p][nf * 16][kk], LDS);
            wmma::mma_sync(acc, af, bf, acc);
        }
        __syncthreads();
    }

    wmma::store_matrix_sync(&sm.ep.R[w][0][0], acc, 32, wmma::mem_row_major);
    __syncthreads();
    combine8(sm.ep.R, sm.ep.F);
    __syncthreads();
}

__global__ __launch_bounds__(256, 3) void persist_kernel(
    const float* __restrict__ Whh_enc, const float* __restrict__ Whh_dec,
    const float* __restrict__ xrev,    const float* __restrict__ few,
    float* __restrict__ out)
{
    __shared__ __align__(16) SMu sm;

    const int tid   = threadIdx.x;
    const int n0    = blockIdx.x * 64;
    const int jbase = blockIdx.x * 16;
    const int eb  = tid >> 4, ejl = tid & 15;
    const int ejg = jbase + ejl;
    const int eidx = eb * V + ejg;

    unsigned nb = 0;
    float c_reg;

    // ---- step 0: h0 from xg (h=c=0) ----
    {
        float4 x4 = *(const float4*)&g_xg[(size_t)(eb * 8) * G4 + (size_t)ejg * 4];
        float4 bb = *(const float4*)&g_bep[ejg * 4];
        float i_ = sigf (x4.x + bb.x);
        float gg = tanhf(x4.z + bb.z);
        float o_ = sigf (x4.w + bb.w);
        c_reg = i_ * gg;
        g_h16[0][eidx] = __float2half(o_ * tanhf(c_reg));
    }
    grid_bar(++nb);

    // ---- steps 1..7 (fc_enc folded into t=7 via register h) ----
    for (int t = 1; t < TT; t++) {
        if (t == 1) compute_f32<true>(sm, Whh_enc, g_h16[0], n0);
        else        compute_f16(sm, g_h16[(t + 1) & 1], n0);

        {
            float4 pre = *(float4*)&sm.ep.F[eb][ejl * 4];
            float4 xg4 = *(const float4*)&g_xg[(size_t)(eb * 8 + t) * G4 + (size_t)ejg * 4];
            float4 bb  = *(const float4*)&g_bep[ejg * 4];
            float i_ = sigf (pre.x + xg4.x + bb.x);
            float f_ = sigf (pre.y + xg4.y + bb.y);
            float gg = tanhf(pre.z + xg4.z + bb.z);
            float o_ = sigf (pre.w + xg4.w + bb.w);
            c_reg = f_ * c_reg + i_ * gg;
            float h = o_ * tanhf(c_reg);
            g_h16[t & 1][eidx] = __float2half(h);
            if (t == TT - 1) {
                // fc_enc partial: 16-lane reduce, one atomicAdd per half-warp
                float pe = h * few[ejg];
#pragma unroll
                for (int off = 8; off; off >>= 1)
                    pe += __shfl_xor_sync(0xffffffffu, pe, off);
                if (ejl == 0) atomicAdd(&out[eb], pe);
            }
        }
        grid_bar(++nb);
    }

    // ---- decoder (reads h7 = buf 1), writes g_hd16 + zeroes g_dec ----
    compute_f32<false>(sm, Whh_dec, g_h16[1], n0);
    {
        float4 pre = *(float4*)&sm.ep.F[eb][ejl * 4];
        float4 bb  = *(const float4*)&g_bdp[ejg * 4];
        float4 ww  = *(const float4*)&g_widp[ejg * 4];
        float bi = pre.x + bb.x, bf_ = pre.y + bb.y;
        float bg = pre.z + bb.z, bo = pre.w + bb.w;
#pragma unroll
        for (int tr = 0; tr < TR; tr++) {
            float xr = xrev[eb * TR + tr];
            float i_ = sigf (bi + xr * ww.x);
            float f_ = sigf (bf_ + xr * ww.y);
            float gg = tanhf(bg + xr * ww.z);
            float o_ = sigf (bo + xr * ww.w);
            float cd = f_ * c_reg + i_ * gg;
            size_t o = (size_t)(eb * TR + tr) * V + ejg;
            g_hd16[o] = __float2half(o_ * tanhf(cd));
            g_dec[o]  = 0.f;                 // pre-zero for fc_dec atomics
        }
    }
}

// =====================================================================
// fc_dec GEMM: BM=64 rows of hd, K-split 8 (grid 54x8 = 432 = one wave),
// atomic-reduce into g_dec (L2-resident).
// =====================================================================
__global__ __launch_bounds__(256)
void gemm_fcdec(const __half* __restrict__ A, const float* __restrict__ Bf,
                float* __restrict__ C, int N, int klen)
{
    constexpr int BM = 64, BK = 32, BNB = 128, LDS = BK + 8;
    __shared__ __align__(16) __half sA[2][BM][LDS];
    __shared__ __align__(16) __half sB[2][BNB][LDS];
    __shared__ __align__(16) float  sC[BM][BNB + 4];

    const int tid   = threadIdx.x;
    const int n0    = blockIdx.x * BNB;
    const int kbase = blockIdx.y * klen;
    const int niter = klen / BK;

    const int w  = tid >> 5;
    const int wm = w >> 2, wn = w & 3;

    wmma::fragment<wmma::accumulator, 16, 16, 16, float> acc[2][2];
#pragma unroll
    for (int i = 0; i < 2; i++)
#pragma unroll
        for (int j = 0; j < 2; j++) wmma::fill_fragment(acc[i][j], 0.0f);

    uint4 rb[2], ra;
    auto load = [&](int k0) {
#pragma unroll
        for (int p = 0; p < 2; p++) {
            int c = tid + p * 256;
            int row = c >> 2, kc = (c & 3) * 8;
            const float* s = Bf + (size_t)(n0 + row) * V + k0 + kc;
            rb[p] = pack8(*(const float4*)s, *(const float4*)(s + 4));
        }
        ra = *(const uint4*)(A + (size_t)(tid >> 2) * V + k0 + (tid & 3) * 8);
    };
    auto store = [&](int buf) {
#pragma unroll
        for (int p = 0; p < 2; p++) {
            int c = tid + p * 256;
            int row = c >> 2, kc = (c & 3) * 8;
            *(uint4*)(&sB[buf][row][kc]) = rb[p];
        }
        *(uint4*)(&sA[buf][tid >> 2][(tid & 3) * 8]) = ra;
    };

    load(kbase);
    store(0);
    if (niter > 1) load(kbase + BK);
    __syncthreads();

    for (int i = 0; i < niter; i++) {
        int p = i & 1;
        if (i + 1 < niter) store(p ^ 1);
        if (i + 2 < niter) load(kbase + (i + 2) * BK);
#pragma unroll
        for (int kk = 0; kk < BK; kk += 16) {
            wmma::fragment<wmma::matrix_a, 16, 16, 16, __half, wmma::row_major> af[2];
            wmma::fragment<wmma::matrix_b, 16, 16, 16, __half, wmma::col_major> bf[2];
#pragma unroll
            for (int i_ = 0; i_ < 2; i_++)
                wmma::load_matrix_sync(af[i_], &sA[p][wm * 32 + i_ * 16][kk], LDS);
#pragma unroll
            for (int j_ = 0; j_ < 2; j_++)
                wmma::load_matrix_sync(bf[j_], &sB[p][wn * 32 + j_ * 16][kk], LDS);
#pragma unroll
            for (int i_ = 0; i_ < 2; i_++)
#pragma unroll
                for (int j_ = 0; j_ < 2; j_++)
                    wmma::mma_sync(acc[i_][j_], af[i_], bf[j_], acc[i_][j_]);
        }
        __syncthreads();
    }

#pragma unroll
    for (int i_ = 0; i_ < 2; i_++)
#pragma unroll
        for (int j_ = 0; j_ < 2; j_++)
            wmma::store_matrix_sync(&sC[wm * 32 + i_ * 16][wn * 32 + j_ * 16],
                                    acc[i_][j_], BNB + 4, wmma::mem_row_major);
    __syncthreads();
    for (int c = tid; c < BM * BNB; c += 256) {
        int m = c / BNB, n = c - m * BNB;
        atomicAdd(&C[(size_t)m * N + n0 + n], sC[m][n]);
    }
}

// =====================================================================
__global__ void dec_out_kernel(const float* __restrict__ fcb,
                               float* __restrict__ out)
{
    int idx = blockIdx.x * 256 + threadIdx.x;   // 64*V exactly
    int m = idx / V, n = idx - m * V;
    float val = g_dec[idx] + fcb[n];
    int b = m >> 2, tr = m & 3;
    size_t base = 16 + (size_t)(b * 12 + tr * 3) * V + n;
    out[base]         = val;
    out[base + V]     = val;
    out[base + 2 * V] = val;
}

// =====================================================================
extern "C" void kernel_launch(void* const* d_in, const int* in_sizes, int n_in,
                              void* d_out, int out_size)
{
    (void)in_sizes; (void)n_in; (void)out_size;
    const float* x        = (const float*)d_in[0];
    const float* x_rev    = (const float*)d_in[1];
    const float* W_ih_enc = (const float*)d_in[2];
    const float* W_hh_enc = (const float*)d_in[3];
    const float* b_enc    = (const float*)d_in[4];
    const float* fc_enc_w = (const float*)d_in[5];
    const float* fc_enc_b = (const float*)d_in[6];
    const float* W_ih_dec = (const float*)d_in[7];
    const float* W_hh_dec = (const float*)d_in[8];
    const float* b_dec    = (const float*)d_in[9];
    const float* fc_dec_w = (const float*)d_in[10];
    const float* fc_dec_b = (const float*)d_in[11];
    float* out = (float*)d_out;

    __half* hd16_p; float* dec_p;
    cudaGetSymbolAddress((void**)&hd16_p, g_hd16);
    cudaGetSymbolAddress((void**)&dec_p,  g_dec);

    // 0) x -> fp16, permuted vectors, barrier reset, out[0..15] = bias
    prep_conv_kernel<<<540, 256>>>(x, b_enc, b_dec, W_ih_dec, fc_enc_b, out);

    // 1) xg = x @ W_ih_enc^T  (BK=32, full-K, direct store, 432 blocks)
    gemm_xg_kernel<<<dim3(G4 / 128, 2), 256>>>(W_ih_enc);

    // 2) persistent kernel: step0 + steps 1..7 (+fc_enc) + decoder
    persist_kernel<<<NBLK, 256>>>(W_hh_enc, W_hh_dec, x_rev, fc_enc_w, out);

    // 3) dec += h_d @ fc_dec_w^T (ksplit 8 = 432 blocks, atomic)
    gemm_fcdec<<<dim3(V / 128, 8), 256>>>(hd16_p, fc_dec_w, dec_p, V, V / 8);
    dec_out_kernel<<<BSZ * TR * V / 256, 256>>>(fc_dec_b, out);
}